// round 5
// baseline (speedup 1.0000x reference)
#include <cuda_runtime.h>
#include <cuda_fp16.h>
#include <cstdint>

#define NMAX 100000
#define INDIM 256

// ---------------- device scratch ----------------
__device__ __half g_h2[NMAX * 64];   // fp16 messages
__device__ float  g_m [NMAX * 64];   // fp32 aggregation accumulator
__device__ float  g_x1[NMAX * 128];
__device__ float  g_x2[NMAX * 64];
__device__ float  g_deg[NMAX];

// ---------------- f32x2 packed math helpers ----------------
__device__ __forceinline__ unsigned long long fma2(unsigned long long a,
                                                   unsigned long long b,
                                                   unsigned long long c) {
    unsigned long long d;
    asm("fma.rn.f32x2 %0, %1, %2, %3;" : "=l"(d) : "l"(a), "l"(b), "l"(c));
    return d;
}
__device__ __forceinline__ float2 unpack2(unsigned long long v) {
    float2 f;
    asm("mov.b64 {%0,%1}, %2;" : "=f"(f.x), "=f"(f.y) : "l"(v));
    return f;
}

// ---------------- small utility kernels ----------------
__global__ void zero4_kernel(float4* __restrict__ p, int n4) {
    int i = blockIdx.x * blockDim.x + threadIdx.x;
    if (i < n4) p[i] = make_float4(0.f, 0.f, 0.f, 0.f);
}

__global__ void degree_kernel(const int* __restrict__ dst, float* __restrict__ deg, int E) {
    int e = blockIdx.x * blockDim.x + threadIdx.x;
    if (e < E) atomicAdd(&deg[dst[e]], 1.0f);
}

__global__ void invdeg_kernel(float* __restrict__ deg, int n) {
    int i = blockIdx.x * blockDim.x + threadIdx.x;
    if (i < n) deg[i] = 1.0f / fmaxf(deg[i], 1.0f);
}

// ---------------- scatter-add: fp16 gather, fp32 red accumulate ----------------
__global__ void scatter64_h_kernel(const uint2* __restrict__ h2u,
                                   const int* __restrict__ src,
                                   const int* __restrict__ dst,
                                   float4* __restrict__ acc,
                                   int E) {
    int i = blockIdx.x * blockDim.x + threadIdx.x;
    int total = E * 16;
    if (i >= total) return;
    int e = i >> 4;
    int j = i & 15;
    int s = __ldg(&src[e]);
    int d = __ldg(&dst[e]);
    uint2 raw = __ldg(&h2u[(size_t)s * 16 + j]);
    __half2 h0 = *(__half2*)&raw.x;
    __half2 h1 = *(__half2*)&raw.y;
    float2 f0 = __half22float2(h0);
    float2 f1 = __half22float2(h1);
    float* p = (float*)&acc[(size_t)d * 16 + j];
    asm volatile("red.global.add.v4.f32 [%0], {%1,%2,%3,%4};"
                 :: "l"(p), "f"(f0.x), "f"(f0.y), "f"(f1.x), "f"(f1.y) : "memory");
}

// ---------------- concat-GEMM, k-pair f32x2 inner loop (no operand dup) -------
// C = act( [A1 | A2*invdeg] @ W + bias )
// acc.x accumulates even-k terms, acc.y odd-k terms; epilogue adds halves.
template<int K1, int K2, int OUT, int BM, bool RELU, bool HALF_OUT>
__global__ __launch_bounds__(256, 2)
void gemm_cat5(const float* __restrict__ A1,
               const float* __restrict__ A2,
               const float* __restrict__ invdeg,
               const float* __restrict__ W,
               const float* __restrict__ bias,
               float* __restrict__ Cf,
               __half* __restrict__ Ch, int n)
{
    constexpr int K      = K1 + K2;
    constexpr int BK     = 32;
    constexpr int KP     = BK / 2;               // k-pairs per stage
    constexpr int TN     = OUT / 16;             // cols per thread (4 or 8)
    constexpr int RP     = BM / 16;              // rows per thread (8 or 4)
    constexpr int NSTAGE = K / BK;
    constexpr int ALOAD  = BM / 32;              // float4 A loads per thread
    constexpr int WLOAD  = (BK * OUT) / 1024;    // float4 W loads per thread

    static_assert(K % BK == 0, "");
    static_assert(K1 % 4 == 0, "");

    __shared__ float As[BM][BK];         // row-major, 128B rows
    __shared__ float Wk[KP][2 * OUT];    // Wk[kp][2c+e] = W[2kp+e][c]

    const int tid  = threadIdx.x;
    const int tx   = tid & 15;
    const int ty   = tid >> 4;
    const int row0 = blockIdx.x * BM;
    const int B    = ty * RP;

    int ar[ALOAD], akc[ALOAD];
#pragma unroll
    for (int p = 0; p < ALOAD; p++) {
        int idx = tid + p * 256;
        ar[p]  = idx >> 3;
        akc[p] = idx & 7;
    }

    unsigned long long acc[RP][TN];
#pragma unroll
    for (int i = 0; i < RP; i++)
#pragma unroll
        for (int j = 0; j < TN; j++) acc[i][j] = 0ull;

    float4 pa[ALOAD];
    float4 pw[WLOAD];

    auto loadA = [&](int kt) {
#pragma unroll
        for (int p = 0; p < ALOAD; p++) {
            int grow = row0 + ar[p];
            int gk   = kt + akc[p] * 4;
            float4 v = make_float4(0.f, 0.f, 0.f, 0.f);
            if (grow < n) {
                if (K2 == 0 || gk < K1) {
                    v = *(const float4*)&A1[(size_t)grow * K1 + gk];
                } else {
                    v = *(const float4*)&A2[(size_t)grow * K2 + (gk - K1)];
                    float s = __ldg(&invdeg[grow]);
                    v.x *= s; v.y *= s; v.z *= s; v.w *= s;
                }
            }
            pa[p] = v;
        }
    };
    auto loadW = [&](int kt) {
#pragma unroll
        for (int q = 0; q < WLOAD; q++) {
            int idx = tid + q * 256;           // float4 units within BKxOUT
            int k   = idx / (OUT / 4);
            int c4  = idx % (OUT / 4);
            pw[q] = *(const float4*)&W[(size_t)(kt + k) * OUT + c4 * 4];
        }
    };

    loadA(0);
    loadW(0);

    for (int s = 0; s < NSTAGE; s++) {
        // commit A tile
#pragma unroll
        for (int p = 0; p < ALOAD; p++)
            *(float4*)&As[ar[p]][akc[p] * 4] = pa[p];
        // commit W tile, k-pair interleaved: Wk[k>>1][2c + (k&1)]
#pragma unroll
        for (int q = 0; q < WLOAD; q++) {
            int idx = tid + q * 256;
            int k   = idx / (OUT / 4);
            int c4  = idx % (OUT / 4);
            int kp  = k >> 1;
            int e   = k & 1;
            float* wrow = &Wk[kp][0];
            wrow[8 * c4 + 0 + e] = pw[q].x;
            wrow[8 * c4 + 2 + e] = pw[q].y;
            wrow[8 * c4 + 4 + e] = pw[q].z;
            wrow[8 * c4 + 6 + e] = pw[q].w;
        }
        __syncthreads();

        if (s + 1 < NSTAGE) {                  // overlap next LDG with compute
            loadA((s + 1) * BK);
            loadW((s + 1) * BK);
        }

#pragma unroll
        for (int kp = 0; kp < KP; kp++) {
            unsigned long long bp[TN];
            const ulonglong2* brow = (const ulonglong2*)&Wk[kp][2 * tx * TN];
#pragma unroll
            for (int j2 = 0; j2 < TN / 2; j2++) {
                ulonglong2 b = brow[j2];       // LDS.128: two k-pairs
                bp[2 * j2]     = b.x;
                bp[2 * j2 + 1] = b.y;
            }
#pragma unroll
            for (int i = 0; i < RP; i++) {
                unsigned long long a =
                    *(const unsigned long long*)&As[B + i][2 * kp];  // LDS.64
#pragma unroll
                for (int j = 0; j < TN; j++)
                    acc[i][j] = fma2(a, bp[j], acc[i][j]);
            }
        }
        __syncthreads();
    }

    // ---- epilogue: horizontal add, bias, activation, vector store ----
    float bv[TN];
#pragma unroll
    for (int j = 0; j < TN; j++) bv[j] = bias[tx * TN + j];

#pragma unroll
    for (int i = 0; i < RP; i++) {
        int grow = row0 + B + i;
        if (grow >= n) continue;
        float v[TN];
#pragma unroll
        for (int j = 0; j < TN; j++) {
            float2 f = unpack2(acc[i][j]);
            float r = f.x + f.y + bv[j];
            if (RELU) r = fmaxf(r, 0.f);
            v[j] = r;
        }
        if constexpr (HALF_OUT) {
#pragma unroll
            for (int j2 = 0; j2 < TN / 2; j2++) {
                __half2* dst2 = (__half2*)&Ch[(size_t)grow * OUT + tx * TN + 2 * j2];
                *dst2 = __floats2half2_rn(v[2 * j2], v[2 * j2 + 1]);
            }
        } else {
#pragma unroll
            for (int j4 = 0; j4 < TN / 4; j4++)
                *(float4*)&Cf[(size_t)grow * OUT + tx * TN + 4 * j4] =
                    make_float4(v[j4 * 4], v[j4 * 4 + 1], v[j4 * 4 + 2], v[j4 * 4 + 3]);
        }
    }
}

// ---------------- head: out = relu(x2 @ Wl1 + bl1) @ Wl2 + bl2 ----------------
__global__ void head_kernel(const float* __restrict__ x2,
                            const float* __restrict__ Wl1,
                            const float* __restrict__ bl1,
                            const float* __restrict__ Wl2,
                            const float* __restrict__ bl2,
                            float* __restrict__ out, int n)
{
    int gtid = blockIdx.x * blockDim.x + threadIdx.x;
    int row  = gtid >> 5;
    int lane = gtid & 31;
    if (row >= n) return;

    const float* xr = x2 + (size_t)row * 64;
    float acc = 0.f;
#pragma unroll
    for (int k = 0; k < 64; k++)
        acc = fmaf(__ldg(&xr[k]), __ldg(&Wl1[k * 32 + lane]), acc);
    float h = fmaxf(acc + __ldg(&bl1[lane]), 0.f);
    float p = h * __ldg(&Wl2[lane]);
#pragma unroll
    for (int off = 16; off; off >>= 1)
        p += __shfl_down_sync(0xffffffffu, p, off);
    if (lane == 0) out[row] = p + __ldg(&bl2[0]);
}

// ---------------- launch ----------------
extern "C" void kernel_launch(void* const* d_in, const int* in_sizes, int n_in,
                              void* d_out, int out_size)
{
    const float* x    = (const float*)d_in[0];
    const int*   ei   = (const int*)  d_in[1];
    const float* W1a  = (const float*)d_in[3];
    const float* b1a  = (const float*)d_in[4];
    const float* W1b  = (const float*)d_in[5];
    const float* b1b  = (const float*)d_in[6];
    const float* W2a  = (const float*)d_in[7];
    const float* b2a  = (const float*)d_in[8];
    const float* W2b  = (const float*)d_in[9];
    const float* b2b  = (const float*)d_in[10];
    const float* Wl1  = (const float*)d_in[11];
    const float* bl1  = (const float*)d_in[12];
    const float* Wl2  = (const float*)d_in[13];
    const float* bl2  = (const float*)d_in[14];
    float* out = (float*)d_out;

    const int N = in_sizes[0] / INDIM;
    const int E = in_sizes[1] / 2;
    const int* src = ei;
    const int* dst = ei + E;

    __half *h2;
    float *m, *x1, *x2, *deg;
    cudaGetSymbolAddress((void**)&h2,  g_h2);
    cudaGetSymbolAddress((void**)&m,   g_m);
    cudaGetSymbolAddress((void**)&x1,  g_x1);
    cudaGetSymbolAddress((void**)&x2,  g_x2);
    cudaGetSymbolAddress((void**)&deg, g_deg);

    const int T = 256;
    auto blocks = [](long long work, int t) { return (int)((work + t - 1) / t); };

    // degree (shared by both layers)
    zero4_kernel<<<blocks((N + 3) / 4, T), T>>>((float4*)deg, (N + 3) / 4);
    degree_kernel<<<blocks(E, T), T>>>(dst, deg, E);
    invdeg_kernel<<<blocks(N, T), T>>>(deg, N);

    // ---- layer 1 ----
    zero4_kernel<<<blocks((long long)N * 16, T), T>>>((float4*)m, N * 16);
    gemm_cat5<256, 0, 64, 128, false, true><<<blocks(N, 128), 256>>>(
        x, nullptr, nullptr, W1a, b1a, nullptr, h2, N);
    scatter64_h_kernel<<<blocks((long long)E * 16, T), T>>>(
        (const uint2*)h2, src, dst, (float4*)m, E);
    gemm_cat5<256, 64, 128, 64, true, false><<<blocks(N, 64), 256>>>(
        x, m, deg, W1b, b1b, x1, nullptr, N);

    // ---- layer 2 ----
    zero4_kernel<<<blocks((long long)N * 16, T), T>>>((float4*)m, N * 16);
    gemm_cat5<128, 0, 64, 128, false, true><<<blocks(N, 128), 256>>>(
        x1, nullptr, nullptr, W2a, b2a, nullptr, h2, N);
    scatter64_h_kernel<<<blocks((long long)E * 16, T), T>>>(
        (const uint2*)h2, src, dst, (float4*)m, E);
    gemm_cat5<128, 64, 64, 128, true, false><<<blocks(N, 128), 256>>>(
        x1, m, deg, W2b, b2b, x2, nullptr, N);

    // ---- head ----
    head_kernel<<<blocks((long long)N * 32, T), T>>>(x2, Wl1, bl1, Wl2, bl2, out, N);
}

// round 6
// speedup vs baseline: 1.7951x; 1.7951x over previous
#include <cuda_runtime.h>
#include <cuda_bf16.h>
#include <cuda_fp16.h>
#include <cstdint>

#define NMAX 100000

// ---------------- device scratch ----------------
__device__ __nv_bfloat16 g_AhL1[NMAX * 320];
__device__ __nv_bfloat16 g_AlL1[NMAX * 320];
__device__ __nv_bfloat16 g_AhL2[NMAX * 192];
__device__ __nv_bfloat16 g_AlL2[NMAX * 192];
__device__ __nv_bfloat16 g_Wh[320 * 128];
__device__ __nv_bfloat16 g_Wl[320 * 128];
__device__ __half g_h2[NMAX * 64];
__device__ float  g_m [NMAX * 64];
__device__ float  g_x2[NMAX * 64];
__device__ float  g_deg[NMAX];

// ---------------- helpers ----------------
__device__ __forceinline__ uint32_t smem_u32(const void* p) {
    uint32_t a;
    asm("{ .reg .u64 t; cvta.to.shared.u64 t, %1; cvt.u32.u64 %0, t; }"
        : "=r"(a) : "l"(p));
    return a;
}
__device__ __forceinline__ void ldmx4(uint32_t& r0, uint32_t& r1, uint32_t& r2,
                                      uint32_t& r3, uint32_t addr) {
    asm volatile("ldmatrix.sync.aligned.m8n8.x4.shared.b16 {%0,%1,%2,%3}, [%4];"
                 : "=r"(r0), "=r"(r1), "=r"(r2), "=r"(r3) : "r"(addr));
}
__device__ __forceinline__ void ldmx4t(uint32_t& r0, uint32_t& r1, uint32_t& r2,
                                       uint32_t& r3, uint32_t addr) {
    asm volatile("ldmatrix.sync.aligned.m8n8.x4.trans.shared.b16 {%0,%1,%2,%3}, [%4];"
                 : "=r"(r0), "=r"(r1), "=r"(r2), "=r"(r3) : "r"(addr));
}
__device__ __forceinline__ void mma_bf16(float* d,
                                         uint32_t a0, uint32_t a1, uint32_t a2, uint32_t a3,
                                         uint32_t b0, uint32_t b1) {
    asm volatile("mma.sync.aligned.m16n8k16.row.col.f32.bf16.bf16.f32 "
                 "{%0,%1,%2,%3}, {%4,%5,%6,%7}, {%8,%9}, {%0,%1,%2,%3};"
                 : "+f"(d[0]), "+f"(d[1]), "+f"(d[2]), "+f"(d[3])
                 : "r"(a0), "r"(a1), "r"(a2), "r"(a3), "r"(b0), "r"(b1));
}

// ---------------- utility kernels ----------------
__global__ void zero4_kernel(float4* __restrict__ p, int n4) {
    int i = blockIdx.x * blockDim.x + threadIdx.x;
    if (i < n4) p[i] = make_float4(0.f, 0.f, 0.f, 0.f);
}
__global__ void degree_kernel(const int* __restrict__ dst, float* __restrict__ deg, int E) {
    int e = blockIdx.x * blockDim.x + threadIdx.x;
    if (e < E) atomicAdd(&deg[dst[e]], 1.0f);
}
__global__ void invdeg_kernel(float* __restrict__ deg, int n) {
    int i = blockIdx.x * blockDim.x + threadIdx.x;
    if (i < n) deg[i] = 1.0f / fmaxf(deg[i], 1.0f);
}

// ---------------- fp32 -> bf16 hi/lo plane split ----------------
// src: [n][SK] fp32 (row-major, contiguous). dst planes: [n][LD] at COLOFF.
template<int SK, int LD, int COLOFF, bool SCALE>
__global__ void cvt_plane_kernel(const float4* __restrict__ src,
                                 const float* __restrict__ scale,
                                 __nv_bfloat16* __restrict__ hi,
                                 __nv_bfloat16* __restrict__ lo,
                                 int n) {
    int i = blockIdx.x * blockDim.x + threadIdx.x;
    int tot = n * (SK / 4);
    if (i >= tot) return;
    int r  = i / (SK / 4);
    int c4 = i % (SK / 4);
    float4 v = __ldg(&src[i]);
    if (SCALE) {
        float s = __ldg(&scale[r]);
        v.x *= s; v.y *= s; v.z *= s; v.w *= s;
    }
    __nv_bfloat16 h0 = __float2bfloat16(v.x), h1 = __float2bfloat16(v.y);
    __nv_bfloat16 h2 = __float2bfloat16(v.z), h3 = __float2bfloat16(v.w);
    __nv_bfloat16 l0 = __float2bfloat16(v.x - __bfloat162float(h0));
    __nv_bfloat16 l1 = __float2bfloat16(v.y - __bfloat162float(h1));
    __nv_bfloat16 l2 = __float2bfloat16(v.z - __bfloat162float(h2));
    __nv_bfloat16 l3 = __float2bfloat16(v.w - __bfloat162float(h3));
    size_t off = (size_t)r * LD + COLOFF + c4 * 4;
    __nv_bfloat162 ph0; ph0.x = h0; ph0.y = h1;
    __nv_bfloat162 ph1; ph1.x = h2; ph1.y = h3;
    __nv_bfloat162 pl0; pl0.x = l0; pl0.y = l1;
    __nv_bfloat162 pl1; pl1.x = l2; pl1.y = l3;
    *(__nv_bfloat162*)(hi + off)     = ph0;
    *(__nv_bfloat162*)(hi + off + 2) = ph1;
    *(__nv_bfloat162*)(lo + off)     = pl0;
    *(__nv_bfloat162*)(lo + off + 2) = pl1;
}

// ---------------- scatter-add: fp16 gather, fp32 red accumulate ----------------
__global__ void scatter64_h_kernel(const uint2* __restrict__ h2u,
                                   const int* __restrict__ src,
                                   const int* __restrict__ dst,
                                   float4* __restrict__ acc,
                                   int E) {
    int i = blockIdx.x * blockDim.x + threadIdx.x;
    int total = E * 16;
    if (i >= total) return;
    int e = i >> 4;
    int j = i & 15;
    int s = __ldg(&src[e]);
    int d = __ldg(&dst[e]);
    uint2 raw = __ldg(&h2u[(size_t)s * 16 + j]);
    __half2 h0 = *(__half2*)&raw.x;
    __half2 h1 = *(__half2*)&raw.y;
    float2 f0 = __half22float2(h0);
    float2 f1 = __half22float2(h1);
    float* p = (float*)&acc[(size_t)d * 16 + j];
    asm volatile("red.global.add.v4.f32 [%0], {%1,%2,%3,%4};"
                 :: "l"(p), "f"(f0.x), "f"(f0.y), "f"(f1.x), "f"(f1.y) : "memory");
}

// ---------------- split-bf16 tensor-core GEMM ----------------
// C = act( (Ah+Al) @ (Wh+Wl) + bias )  via  Ah·Wh + Ah·Wl + Al·Wh
// output: 0 = fp32 Cf, 1 = fp16 Ch, 2 = bf16 hi/lo planes (Oh/Ol, LDOUT)
template<int K, int OUT, int LDIN, int OMODE, int LDOUT, bool RELU>
__global__ __launch_bounds__(256, 2)
void gemm_mma(const __nv_bfloat16* __restrict__ Ah,
              const __nv_bfloat16* __restrict__ Al,
              const __nv_bfloat16* __restrict__ Wh,
              const __nv_bfloat16* __restrict__ Wl,
              const float* __restrict__ bias,
              float* __restrict__ Cf, __half* __restrict__ Ch,
              __nv_bfloat16* __restrict__ Oh, __nv_bfloat16* __restrict__ Ol,
              int n)
{
    constexpr int BM    = (OUT == 128) ? 64 : 128;
    constexpr int BK    = 32;
    constexpr int APAD  = 40;        // halves per A smem row (bank-spread)
    constexpr int WPAD  = OUT + 8;   // halves per W smem row
    constexpr int NSTG  = K / BK;
    constexpr int NWROW = BM / 16;   // warps along M
    constexpr int AU    = (BM * BK) / (8 * 256);   // uint4 A loads/plane/thread
    constexpr int WU    = (BK * OUT) / (8 * 256);  // uint4 W loads/plane/thread

    static_assert(K % BK == 0, "");

    __shared__ __align__(16) __nv_bfloat16 AsH[BM * APAD];
    __shared__ __align__(16) __nv_bfloat16 AsL[BM * APAD];
    __shared__ __align__(16) __nv_bfloat16 WsH[BK * WPAD];
    __shared__ __align__(16) __nv_bfloat16 WsL[BK * WPAD];

    const int tid  = threadIdx.x;
    const int w    = tid >> 5;
    const int lane = tid & 31;
    const int wr   = w % NWROW;
    const int wc   = w / NWROW;
    const int row0 = blockIdx.x * BM;

    float d[8][4];
#pragma unroll
    for (int j = 0; j < 8; j++)
#pragma unroll
        for (int q = 0; q < 4; q++) d[j][q] = 0.f;

    uint4 paH[AU], paL[AU], pwH[WU], pwL[WU];

    auto loadA = [&](int kt) {
#pragma unroll
        for (int p = 0; p < AU; p++) {
            int idx = tid + p * 256;
            int r   = idx >> 2;         // BK/8 = 4 uint4 per row
            int c8  = idx & 3;
            int grow = row0 + r;
            if (grow < n) {
                size_t off = (size_t)grow * LDIN + kt + c8 * 8;
                paH[p] = *(const uint4*)(Ah + off);
                paL[p] = *(const uint4*)(Al + off);
            } else {
                paH[p] = make_uint4(0, 0, 0, 0);
                paL[p] = make_uint4(0, 0, 0, 0);
            }
        }
    };
    auto loadW = [&](int kt) {
#pragma unroll
        for (int q = 0; q < WU; q++) {
            int idx = tid + q * 256;
            int k   = idx / (OUT / 8);
            int c8  = idx % (OUT / 8);
            size_t off = (size_t)(kt + k) * OUT + c8 * 8;
            pwH[q] = *(const uint4*)(Wh + off);
            pwL[q] = *(const uint4*)(Wl + off);
        }
    };

    loadA(0);
    loadW(0);

    // lane-constant ldmatrix geometry
    const int quad = lane >> 3;
    const int l8   = lane & 7;
    const uint32_t asH = smem_u32(AsH), asL = smem_u32(AsL);
    const uint32_t wsH = smem_u32(WsH), wsL = smem_u32(WsL);
    const int aRow  = 16 * wr + (quad & 1) * 8 + l8;
    const int aColQ = (quad >> 1) * 8;
    const int bRowQ = (quad & 1) * 8 + l8;
    const int bColQ = 64 * wc + (quad >> 1) * 8;

    for (int s = 0; s < NSTG; s++) {
        // commit prefetched tiles
#pragma unroll
        for (int p = 0; p < AU; p++) {
            int idx = tid + p * 256;
            int r = idx >> 2, c8 = idx & 3;
            *(uint4*)(AsH + r * APAD + c8 * 8) = paH[p];
            *(uint4*)(AsL + r * APAD + c8 * 8) = paL[p];
        }
#pragma unroll
        for (int q = 0; q < WU; q++) {
            int idx = tid + q * 256;
            int k = idx / (OUT / 8), c8 = idx % (OUT / 8);
            *(uint4*)(WsH + k * WPAD + c8 * 8) = pwH[q];
            *(uint4*)(WsL + k * WPAD + c8 * 8) = pwL[q];
        }
        __syncthreads();

        if (s + 1 < NSTG) { loadA((s + 1) * BK); loadW((s + 1) * BK); }

#pragma unroll
        for (int kk = 0; kk < BK; kk += 16) {
            uint32_t ah0, ah1, ah2, ah3, al0, al1, al2, al3;
            uint32_t aoff = (uint32_t)(aRow * APAD + kk + aColQ) * 2;
            ldmx4(ah0, ah1, ah2, ah3, asH + aoff);
            ldmx4(al0, al1, al2, al3, asL + aoff);
#pragma unroll
            for (int pr = 0; pr < 4; pr++) {
                uint32_t boff = (uint32_t)((kk + bRowQ) * WPAD + bColQ + 16 * pr) * 2;
                uint32_t bh0, bh1, bh2, bh3, bl0, bl1, bl2, bl3;
                ldmx4t(bh0, bh1, bh2, bh3, wsH + boff);
                ldmx4t(bl0, bl1, bl2, bl3, wsL + boff);
                mma_bf16(d[2 * pr],     ah0, ah1, ah2, ah3, bh0, bh1);
                mma_bf16(d[2 * pr],     ah0, ah1, ah2, ah3, bl0, bl1);
                mma_bf16(d[2 * pr],     al0, al1, al2, al3, bh0, bh1);
                mma_bf16(d[2 * pr + 1], ah0, ah1, ah2, ah3, bh2, bh3);
                mma_bf16(d[2 * pr + 1], ah0, ah1, ah2, ah3, bl2, bl3);
                mma_bf16(d[2 * pr + 1], al0, al1, al2, al3, bh2, bh3);
            }
        }
        __syncthreads();
    }

    // ---- epilogue ----
    const int tr = lane >> 2;
    const int tc = (lane & 3) * 2;
#pragma unroll
    for (int j = 0; j < 8; j++) {
        int c = 64 * wc + 8 * j + tc;
        float b0 = __ldg(&bias[c]);
        float b1 = __ldg(&bias[c + 1]);
#pragma unroll
        for (int half = 0; half < 2; half++) {
            int r = row0 + 16 * wr + tr + 8 * half;
            if (r >= n) continue;
            float v0 = d[j][2 * half]     + b0;
            float v1 = d[j][2 * half + 1] + b1;
            if (RELU) { v0 = fmaxf(v0, 0.f); v1 = fmaxf(v1, 0.f); }
            if constexpr (OMODE == 0) {
                *(float2*)&Cf[(size_t)r * OUT + c] = make_float2(v0, v1);
            } else if constexpr (OMODE == 1) {
                *(__half2*)&Ch[(size_t)r * OUT + c] = __floats2half2_rn(v0, v1);
            } else {
                __nv_bfloat16 h0 = __float2bfloat16(v0);
                __nv_bfloat16 h1 = __float2bfloat16(v1);
                __nv_bfloat16 l0 = __float2bfloat16(v0 - __bfloat162float(h0));
                __nv_bfloat16 l1 = __float2bfloat16(v1 - __bfloat162float(h1));
                __nv_bfloat162 ph; ph.x = h0; ph.y = h1;
                __nv_bfloat162 pl; pl.x = l0; pl.y = l1;
                *(__nv_bfloat162*)(Oh + (size_t)r * LDOUT + c) = ph;
                *(__nv_bfloat162*)(Ol + (size_t)r * LDOUT + c) = pl;
            }
        }
    }
}

// ---------------- head ----------------
__global__ void head_kernel(const float* __restrict__ x2,
                            const float* __restrict__ Wl1,
                            const float* __restrict__ bl1,
                            const float* __restrict__ Wl2,
                            const float* __restrict__ bl2,
                            float* __restrict__ out, int n)
{
    int gtid = blockIdx.x * blockDim.x + threadIdx.x;
    int row  = gtid >> 5;
    int lane = gtid & 31;
    if (row >= n) return;
    const float* xr = x2 + (size_t)row * 64;
    float acc = 0.f;
#pragma unroll
    for (int k = 0; k < 64; k++)
        acc = fmaf(__ldg(&xr[k]), __ldg(&Wl1[k * 32 + lane]), acc);
    float h = fmaxf(acc + __ldg(&bl1[lane]), 0.f);
    float p = h * __ldg(&Wl2[lane]);
#pragma unroll
    for (int off = 16; off; off >>= 1)
        p += __shfl_down_sync(0xffffffffu, p, off);
    if (lane == 0) out[row] = p + __ldg(&bl2[0]);
}

// ---------------- launch ----------------
extern "C" void kernel_launch(void* const* d_in, const int* in_sizes, int n_in,
                              void* d_out, int out_size)
{
    const float* x    = (const float*)d_in[0];
    const int*   ei   = (const int*)  d_in[1];
    const float* W1a  = (const float*)d_in[3];
    const float* b1a  = (const float*)d_in[4];
    const float* W1b  = (const float*)d_in[5];
    const float* b1b  = (const float*)d_in[6];
    const float* W2a  = (const float*)d_in[7];
    const float* b2a  = (const float*)d_in[8];
    const float* W2b  = (const float*)d_in[9];
    const float* b2b  = (const float*)d_in[10];
    const float* Wl1  = (const float*)d_in[11];
    const float* bl1  = (const float*)d_in[12];
    const float* Wl2  = (const float*)d_in[13];
    const float* bl2  = (const float*)d_in[14];
    float* out = (float*)d_out;

    const int N = in_sizes[0] / 256;
    const int E = in_sizes[1] / 2;
    const int* src = ei;
    const int* dst = ei + E;

    __nv_bfloat16 *ah1, *al1, *ah2, *al2, *wh, *wl;
    __half* h2;
    float *m, *x2, *deg;
    cudaGetSymbolAddress((void**)&ah1, g_AhL1);
    cudaGetSymbolAddress((void**)&al1, g_AlL1);
    cudaGetSymbolAddress((void**)&ah2, g_AhL2);
    cudaGetSymbolAddress((void**)&al2, g_AlL2);
    cudaGetSymbolAddress((void**)&wh,  g_Wh);
    cudaGetSymbolAddress((void**)&wl,  g_Wl);
    cudaGetSymbolAddress((void**)&h2,  g_h2);
    cudaGetSymbolAddress((void**)&m,   g_m);
    cudaGetSymbolAddress((void**)&x2,  g_x2);
    cudaGetSymbolAddress((void**)&deg, g_deg);

    const int T = 256;
    auto blocks = [](long long work, int t) { return (int)((work + t - 1) / t); };

    // degree (shared by both layers)
    zero4_kernel<<<blocks((N + 3) / 4, T), T>>>((float4*)deg, (N + 3) / 4);
    degree_kernel<<<blocks(E, T), T>>>(dst, deg, E);
    invdeg_kernel<<<blocks(N, T), T>>>(deg, N);

    // ---- layer 1 ----
    zero4_kernel<<<blocks((long long)N * 16, T), T>>>((float4*)m, N * 16);
    cvt_plane_kernel<256, 320, 0, false><<<blocks((long long)N * 64, T), T>>>(
        (const float4*)x, nullptr, ah1, al1, N);
    cvt_plane_kernel<64, 64, 0, false><<<blocks(256 * 16, T), T>>>(
        (const float4*)W1a, nullptr, wh, wl, 256);
    gemm_mma<256, 64, 320, 1, 0, false><<<blocks(N, 128), 256>>>(
        ah1, al1, wh, wl, b1a, nullptr, h2, nullptr, nullptr, N);
    scatter64_h_kernel<<<blocks((long long)E * 16, T), T>>>(
        (const uint2*)h2, src, dst, (float4*)m, E);
    cvt_plane_kernel<64, 320, 256, true><<<blocks((long long)N * 16, T), T>>>(
        (const float4*)m, deg, ah1, al1, N);
    cvt_plane_kernel<128, 128, 0, false><<<blocks(320 * 32, T), T>>>(
        (const float4*)W1b, nullptr, wh, wl, 320);
    gemm_mma<320, 128, 320, 2, 192, true><<<blocks(N, 64), 256>>>(
        ah1, al1, wh, wl, b1b, nullptr, nullptr, ah2, al2, N);

    // ---- layer 2 ----
    zero4_kernel<<<blocks((long long)N * 16, T), T>>>((float4*)m, N * 16);
    cvt_plane_kernel<64, 64, 0, false><<<blocks(128 * 16, T), T>>>(
        (const float4*)W2a, nullptr, wh, wl, 128);
    gemm_mma<128, 64, 192, 1, 0, false><<<blocks(N, 128), 256>>>(
        ah2, al2, wh, wl, b2a, nullptr, h2, nullptr, nullptr, N);
    scatter64_h_kernel<<<blocks((long long)E * 16, T), T>>>(
        (const uint2*)h2, src, dst, (float4*)m, E);
    cvt_plane_kernel<64, 192, 128, true><<<blocks((long long)N * 16, T), T>>>(
        (const float4*)m, deg, ah2, al2, N);
    cvt_plane_kernel<64, 64, 0, false><<<blocks(192 * 16, T), T>>>(
        (const float4*)W2b, nullptr, wh, wl, 192);
    gemm_mma<192, 64, 192, 0, 0, true><<<blocks(N, 128), 256>>>(
        ah2, al2, wh, wl, b2b, x2, nullptr, nullptr, nullptr, N);

    // ---- head ----
    head_kernel<<<blocks((long long)N * 32, T), T>>>(x2, Wl1, bl1, Wl2, bl2, out, N);
}

// round 7
// speedup vs baseline: 2.3158x; 1.2901x over previous
#include <cuda_runtime.h>
#include <cuda_bf16.h>
#include <cuda_fp16.h>
#include <cstdint>

#define NMAX 100000
#define EMAX 3200000

// ---------------- device scratch ----------------
__device__ __nv_bfloat16 g_AhL1[NMAX * 320];
__device__ __nv_bfloat16 g_AlL1[NMAX * 320];
__device__ __nv_bfloat16 g_AhL2[NMAX * 192];
__device__ __nv_bfloat16 g_AlL2[NMAX * 192];
__device__ __nv_bfloat16 g_Wh[77824];
__device__ __nv_bfloat16 g_Wl[77824];
__device__ __half g_h2[NMAX * 64];
__device__ float  g_x2[NMAX * 64];
__device__ int    g_cnt[NMAX];
__device__ int    g_cursor[NMAX];
__device__ int    g_rowstart[NMAX + 1];
__device__ int    g_colsrc[EMAX];

// ---------------- mma helpers ----------------
__device__ __forceinline__ uint32_t smem_u32(const void* p) {
    uint32_t a;
    asm("{ .reg .u64 t; cvta.to.shared.u64 t, %1; cvt.u32.u64 %0, t; }"
        : "=r"(a) : "l"(p));
    return a;
}
__device__ __forceinline__ void ldmx4(uint32_t& r0, uint32_t& r1, uint32_t& r2,
                                      uint32_t& r3, uint32_t addr) {
    asm volatile("ldmatrix.sync.aligned.m8n8.x4.shared.b16 {%0,%1,%2,%3}, [%4];"
                 : "=r"(r0), "=r"(r1), "=r"(r2), "=r"(r3) : "r"(addr));
}
__device__ __forceinline__ void ldmx4t(uint32_t& r0, uint32_t& r1, uint32_t& r2,
                                       uint32_t& r3, uint32_t addr) {
    asm volatile("ldmatrix.sync.aligned.m8n8.x4.trans.shared.b16 {%0,%1,%2,%3}, [%4];"
                 : "=r"(r0), "=r"(r1), "=r"(r2), "=r"(r3) : "r"(addr));
}
__device__ __forceinline__ void mma_bf16(float* d,
                                         uint32_t a0, uint32_t a1, uint32_t a2, uint32_t a3,
                                         uint32_t b0, uint32_t b1) {
    asm volatile("mma.sync.aligned.m16n8k16.row.col.f32.bf16.bf16.f32 "
                 "{%0,%1,%2,%3}, {%4,%5,%6,%7}, {%8,%9}, {%0,%1,%2,%3};"
                 : "+f"(d[0]), "+f"(d[1]), "+f"(d[2]), "+f"(d[3])
                 : "r"(a0), "r"(a1), "r"(a2), "r"(a3), "r"(b0), "r"(b1));
}

// ---------------- CSR build kernels ----------------
__global__ void zero_int_kernel(int* __restrict__ p, int n) {
    int i = blockIdx.x * blockDim.x + threadIdx.x;
    if (i < n) p[i] = 0;
}
__global__ void count_kernel(const int* __restrict__ dst, int* __restrict__ cnt, int E) {
    int e = blockIdx.x * blockDim.x + threadIdx.x;
    if (e < E) atomicAdd(&cnt[dst[e]], 1);
}
// single-block inclusive scan -> rowstart (exclusive via +1 offset) and cursor
__global__ void scan_kernel(const int* __restrict__ cnt,
                            int* __restrict__ rowstart,
                            int* __restrict__ cursor, int n) {
    __shared__ int wsum[32];
    __shared__ int carry_s;
    int tid = threadIdx.x, lane = tid & 31, wid = tid >> 5;
    if (tid == 0) { carry_s = 0; rowstart[0] = 0; }
    __syncthreads();
    for (int base = 0; base < n; base += 1024) {
        int i = base + tid;
        int v = (i < n) ? cnt[i] : 0;
        int x = v;
#pragma unroll
        for (int off = 1; off < 32; off <<= 1) {
            int t = __shfl_up_sync(0xffffffffu, x, off);
            if (lane >= off) x += t;
        }
        if (lane == 31) wsum[wid] = x;
        __syncthreads();
        if (wid == 0) {
            int w = wsum[lane];
#pragma unroll
            for (int off = 1; off < 32; off <<= 1) {
                int t = __shfl_up_sync(0xffffffffu, w, off);
                if (lane >= off) w += t;
            }
            wsum[lane] = w;
        }
        __syncthreads();
        int woff = (wid > 0) ? wsum[wid - 1] : 0;
        int inc  = x + woff + carry_s;
        if (i < n) { rowstart[i + 1] = inc; cursor[i] = inc - v; }
        __syncthreads();
        if (tid == 1023) carry_s = inc;
        __syncthreads();
    }
}
__global__ void fill_kernel(const int* __restrict__ src, const int* __restrict__ dst,
                            int* __restrict__ cursor, int* __restrict__ colsrc, int E) {
    int e = blockIdx.x * blockDim.x + threadIdx.x;
    if (e >= E) return;
    int pos = atomicAdd(&cursor[dst[e]], 1);
    colsrc[pos] = src[e];
}

// ---------------- fp32 -> bf16 hi/lo plane split (node features) -------------
template<int SK, int LD, int COLOFF>
__global__ void cvt_plane_kernel(const float4* __restrict__ src,
                                 __nv_bfloat16* __restrict__ hi,
                                 __nv_bfloat16* __restrict__ lo,
                                 int n) {
    int i = blockIdx.x * blockDim.x + threadIdx.x;
    int tot = n * (SK / 4);
    if (i >= tot) return;
    int r  = i / (SK / 4);
    int c4 = i % (SK / 4);
    float4 v = __ldg(&src[i]);
    __nv_bfloat16 h0 = __float2bfloat16(v.x), h1 = __float2bfloat16(v.y);
    __nv_bfloat16 h2 = __float2bfloat16(v.z), h3 = __float2bfloat16(v.w);
    __nv_bfloat16 l0 = __float2bfloat16(v.x - __bfloat162float(h0));
    __nv_bfloat16 l1 = __float2bfloat16(v.y - __bfloat162float(h1));
    __nv_bfloat16 l2 = __float2bfloat16(v.z - __bfloat162float(h2));
    __nv_bfloat16 l3 = __float2bfloat16(v.w - __bfloat162float(h3));
    size_t off = (size_t)r * LD + COLOFF + c4 * 4;
    __nv_bfloat162 ph0; ph0.x = h0; ph0.y = h1;
    __nv_bfloat162 ph1; ph1.x = h2; ph1.y = h3;
    __nv_bfloat162 pl0; pl0.x = l0; pl0.y = l1;
    __nv_bfloat162 pl1; pl1.x = l2; pl1.y = l3;
    *(__nv_bfloat162*)(hi + off)     = ph0;
    *(__nv_bfloat162*)(hi + off + 2) = ph1;
    *(__nv_bfloat162*)(lo + off)     = pl0;
    *(__nv_bfloat162*)(lo + off + 2) = pl1;
}

// ---------------- all-weights bf16 split in one kernel ----------------
__global__ void cvt_weights_kernel(const float4* __restrict__ Wa, int na4,
                                   const float4* __restrict__ Wb, int nb4,
                                   const float4* __restrict__ Wc, int nc4,
                                   const float4* __restrict__ Wd, int nd4,
                                   __nv_bfloat16* __restrict__ hi,
                                   __nv_bfloat16* __restrict__ lo) {
    int i = blockIdx.x * blockDim.x + threadIdx.x;
    int tot = na4 + nb4 + nc4 + nd4;
    if (i >= tot) return;
    float4 v;
    if (i < na4)                  v = __ldg(&Wa[i]);
    else if (i < na4 + nb4)       v = __ldg(&Wb[i - na4]);
    else if (i < na4 + nb4 + nc4) v = __ldg(&Wc[i - na4 - nb4]);
    else                          v = __ldg(&Wd[i - na4 - nb4 - nc4]);
    __nv_bfloat16 h0 = __float2bfloat16(v.x), h1 = __float2bfloat16(v.y);
    __nv_bfloat16 h2 = __float2bfloat16(v.z), h3 = __float2bfloat16(v.w);
    __nv_bfloat16 l0 = __float2bfloat16(v.x - __bfloat162float(h0));
    __nv_bfloat16 l1 = __float2bfloat16(v.y - __bfloat162float(h1));
    __nv_bfloat16 l2 = __float2bfloat16(v.z - __bfloat162float(h2));
    __nv_bfloat16 l3 = __float2bfloat16(v.w - __bfloat162float(h3));
    size_t off = (size_t)i * 4;
    __nv_bfloat162 ph0; ph0.x = h0; ph0.y = h1;
    __nv_bfloat162 ph1; ph1.x = h2; ph1.y = h3;
    __nv_bfloat162 pl0; pl0.x = l0; pl0.y = l1;
    __nv_bfloat162 pl1; pl1.x = l2; pl1.y = l3;
    *(__nv_bfloat162*)(hi + off)     = ph0;
    *(__nv_bfloat162*)(hi + off + 2) = ph1;
    *(__nv_bfloat162*)(lo + off)     = pl0;
    *(__nv_bfloat162*)(lo + off + 2) = pl1;
}

// ---------------- CSR gather-mean: warp per node, fused invdeg + bf16 split ---
template<int LD, int COLOFF>
__global__ void gather_mean_kernel(const __half2* __restrict__ h2,   // [n][32]
                                   const int* __restrict__ rowstart,
                                   const int* __restrict__ colsrc,
                                   __nv_bfloat16* __restrict__ hi,
                                   __nv_bfloat16* __restrict__ lo,
                                   int n) {
    int warp = (blockIdx.x * blockDim.x + threadIdx.x) >> 5;
    int lane = threadIdx.x & 31;
    if (warp >= n) return;
    int start = __ldg(&rowstart[warp]);
    int end   = __ldg(&rowstart[warp + 1]);

    float ax0 = 0.f, ay0 = 0.f, ax1 = 0.f, ay1 = 0.f;
    float ax2 = 0.f, ay2 = 0.f, ax3 = 0.f, ay3 = 0.f;
    int i = start;
    for (; i + 4 <= end; i += 4) {
        int s0 = __ldg(&colsrc[i]);
        int s1 = __ldg(&colsrc[i + 1]);
        int s2 = __ldg(&colsrc[i + 2]);
        int s3 = __ldg(&colsrc[i + 3]);
        float2 v0 = __half22float2(__ldg(&h2[(size_t)s0 * 32 + lane]));
        float2 v1 = __half22float2(__ldg(&h2[(size_t)s1 * 32 + lane]));
        float2 v2 = __half22float2(__ldg(&h2[(size_t)s2 * 32 + lane]));
        float2 v3 = __half22float2(__ldg(&h2[(size_t)s3 * 32 + lane]));
        ax0 += v0.x; ay0 += v0.y;
        ax1 += v1.x; ay1 += v1.y;
        ax2 += v2.x; ay2 += v2.y;
        ax3 += v3.x; ay3 += v3.y;
    }
    for (; i < end; i++) {
        int s = __ldg(&colsrc[i]);
        float2 v = __half22float2(__ldg(&h2[(size_t)s * 32 + lane]));
        ax0 += v.x; ay0 += v.y;
    }
    float sx = (ax0 + ax1) + (ax2 + ax3);
    float sy = (ay0 + ay1) + (ay2 + ay3);
    float inv = 1.0f / fmaxf((float)(end - start), 1.0f);
    sx *= inv; sy *= inv;

    __nv_bfloat16 hx = __float2bfloat16(sx);
    __nv_bfloat16 hy = __float2bfloat16(sy);
    __nv_bfloat16 lx = __float2bfloat16(sx - __bfloat162float(hx));
    __nv_bfloat16 ly = __float2bfloat16(sy - __bfloat162float(hy));
    size_t off = (size_t)warp * LD + COLOFF + 2 * lane;
    __nv_bfloat162 ph; ph.x = hx; ph.y = hy;
    __nv_bfloat162 pl; pl.x = lx; pl.y = ly;
    *(__nv_bfloat162*)(hi + off) = ph;
    *(__nv_bfloat162*)(lo + off) = pl;
}

// ---------------- split-bf16 tensor-core GEMM ----------------
// C = act( (Ah+Al) @ (Wh+Wl) + bias )  via  Ah·Wh + Ah·Wl + Al·Wh
// output: 0 = fp32 Cf, 1 = fp16 Ch, 2 = bf16 hi/lo planes (Oh/Ol, LDOUT)
template<int K, int OUT, int LDIN, int OMODE, int LDOUT, bool RELU>
__global__ __launch_bounds__(256, 2)
void gemm_mma(const __nv_bfloat16* __restrict__ Ah,
              const __nv_bfloat16* __restrict__ Al,
              const __nv_bfloat16* __restrict__ Wh,
              const __nv_bfloat16* __restrict__ Wl,
              const float* __restrict__ bias,
              float* __restrict__ Cf, __half* __restrict__ Ch,
              __nv_bfloat16* __restrict__ Oh, __nv_bfloat16* __restrict__ Ol,
              int n)
{
    constexpr int BM    = (OUT == 128) ? 64 : 128;
    constexpr int BK    = 32;
    constexpr int APAD  = 40;
    constexpr int WPAD  = OUT + 8;
    constexpr int NSTG  = K / BK;
    constexpr int NWROW = BM / 16;
    constexpr int AU    = (BM * BK) / (8 * 256);
    constexpr int WU    = (BK * OUT) / (8 * 256);

    static_assert(K % BK == 0, "");

    __shared__ __align__(16) __nv_bfloat16 AsH[BM * APAD];
    __shared__ __align__(16) __nv_bfloat16 AsL[BM * APAD];
    __shared__ __align__(16) __nv_bfloat16 WsH[BK * WPAD];
    __shared__ __align__(16) __nv_bfloat16 WsL[BK * WPAD];

    const int tid  = threadIdx.x;
    const int w    = tid >> 5;
    const int lane = tid & 31;
    const int wr   = w % NWROW;
    const int wc   = w / NWROW;
    const int row0 = blockIdx.x * BM;

    float d[8][4];
#pragma unroll
    for (int j = 0; j < 8; j++)
#pragma unroll
        for (int q = 0; q < 4; q++) d[j][q] = 0.f;

    uint4 paH[AU], paL[AU], pwH[WU], pwL[WU];

    auto loadA = [&](int kt) {
#pragma unroll
        for (int p = 0; p < AU; p++) {
            int idx = tid + p * 256;
            int r   = idx >> 2;
            int c8  = idx & 3;
            int grow = row0 + r;
            if (grow < n) {
                size_t off = (size_t)grow * LDIN + kt + c8 * 8;
                paH[p] = *(const uint4*)(Ah + off);
                paL[p] = *(const uint4*)(Al + off);
            } else {
                paH[p] = make_uint4(0, 0, 0, 0);
                paL[p] = make_uint4(0, 0, 0, 0);
            }
        }
    };
    auto loadW = [&](int kt) {
#pragma unroll
        for (int q = 0; q < WU; q++) {
            int idx = tid + q * 256;
            int k   = idx / (OUT / 8);
            int c8  = idx % (OUT / 8);
            size_t off = (size_t)(kt + k) * OUT + c8 * 8;
            pwH[q] = *(const uint4*)(Wh + off);
            pwL[q] = *(const uint4*)(Wl + off);
        }
    };

    loadA(0);
    loadW(0);

    const int quad = lane >> 3;
    const int l8   = lane & 7;
    const uint32_t asH = smem_u32(AsH), asL = smem_u32(AsL);
    const uint32_t wsH = smem_u32(WsH), wsL = smem_u32(WsL);
    const int aRow  = 16 * wr + (quad & 1) * 8 + l8;
    const int aColQ = (quad >> 1) * 8;
    const int bRowQ = (quad & 1) * 8 + l8;
    const int bColQ = 64 * wc + (quad >> 1) * 8;

    for (int s = 0; s < NSTG; s++) {
#pragma unroll
        for (int p = 0; p < AU; p++) {
            int idx = tid + p * 256;
            int r = idx >> 2, c8 = idx & 3;
            *(uint4*)(AsH + r * APAD + c8 * 8) = paH[p];
            *(uint4*)(AsL + r * APAD + c8 * 8) = paL[p];
        }
#pragma unroll
        for (int q = 0; q < WU; q++) {
            int idx = tid + q * 256;
            int k = idx / (OUT / 8), c8 = idx % (OUT / 8);
            *(uint4*)(WsH + k * WPAD + c8 * 8) = pwH[q];
            *(uint4*)(WsL + k * WPAD + c8 * 8) = pwL[q];
        }
        __syncthreads();

        if (s + 1 < NSTG) { loadA((s + 1) * BK); loadW((s + 1) * BK); }

#pragma unroll
        for (int kk = 0; kk < BK; kk += 16) {
            uint32_t ah0, ah1, ah2, ah3, al0, al1, al2, al3;
            uint32_t aoff = (uint32_t)(aRow * APAD + kk + aColQ) * 2;
            ldmx4(ah0, ah1, ah2, ah3, asH + aoff);
            ldmx4(al0, al1, al2, al3, asL + aoff);
#pragma unroll
            for (int pr = 0; pr < 4; pr++) {
                uint32_t boff = (uint32_t)((kk + bRowQ) * WPAD + bColQ + 16 * pr) * 2;
                uint32_t bh0, bh1, bh2, bh3, bl0, bl1, bl2, bl3;
                ldmx4t(bh0, bh1, bh2, bh3, wsH + boff);
                ldmx4t(bl0, bl1, bl2, bl3, wsL + boff);
                mma_bf16(d[2 * pr],     ah0, ah1, ah2, ah3, bh0, bh1);
                mma_bf16(d[2 * pr],     ah0, ah1, ah2, ah3, bl0, bl1);
                mma_bf16(d[2 * pr],     al0, al1, al2, al3, bh0, bh1);
                mma_bf16(d[2 * pr + 1], ah0, ah1, ah2, ah3, bh2, bh3);
                mma_bf16(d[2 * pr + 1], ah0, ah1, ah2, ah3, bl2, bl3);
                mma_bf16(d[2 * pr + 1], al0, al1, al2, al3, bh2, bh3);
            }
        }
        __syncthreads();
    }

    const int tr = lane >> 2;
    const int tc = (lane & 3) * 2;
#pragma unroll
    for (int j = 0; j < 8; j++) {
        int c = 64 * wc + 8 * j + tc;
        float b0 = __ldg(&bias[c]);
        float b1 = __ldg(&bias[c + 1]);
#pragma unroll
        for (int half = 0; half < 2; half++) {
            int r = row0 + 16 * wr + tr + 8 * half;
            if (r >= n) continue;
            float v0 = d[j][2 * half]     + b0;
            float v1 = d[j][2 * half + 1] + b1;
            if (RELU) { v0 = fmaxf(v0, 0.f); v1 = fmaxf(v1, 0.f); }
            if constexpr (OMODE == 0) {
                *(float2*)&Cf[(size_t)r * OUT + c] = make_float2(v0, v1);
            } else if constexpr (OMODE == 1) {
                *(__half2*)&Ch[(size_t)r * OUT + c] = __floats2half2_rn(v0, v1);
            } else {
                __nv_bfloat16 h0 = __float2bfloat16(v0);
                __nv_bfloat16 h1 = __float2bfloat16(v1);
                __nv_bfloat16 l0 = __float2bfloat16(v0 - __bfloat162float(h0));
                __nv_bfloat16 l1 = __float2bfloat16(v1 - __bfloat162float(h1));
                __nv_bfloat162 ph; ph.x = h0; ph.y = h1;
                __nv_bfloat162 pl; pl.x = l0; pl.y = l1;
                *(__nv_bfloat162*)(Oh + (size_t)r * LDOUT + c) = ph;
                *(__nv_bfloat162*)(Ol + (size_t)r * LDOUT + c) = pl;
            }
        }
    }
}

// ---------------- head ----------------
__global__ void head_kernel(const float* __restrict__ x2,
                            const float* __restrict__ Wl1,
                            const float* __restrict__ bl1,
                            const float* __restrict__ Wl2,
                            const float* __restrict__ bl2,
                            float* __restrict__ out, int n)
{
    int gtid = blockIdx.x * blockDim.x + threadIdx.x;
    int row  = gtid >> 5;
    int lane = gtid & 31;
    if (row >= n) return;
    const float* xr = x2 + (size_t)row * 64;
    float acc = 0.f;
#pragma unroll
    for (int k = 0; k < 64; k++)
        acc = fmaf(__ldg(&xr[k]), __ldg(&Wl1[k * 32 + lane]), acc);
    float h = fmaxf(acc + __ldg(&bl1[lane]), 0.f);
    float p = h * __ldg(&Wl2[lane]);
#pragma unroll
    for (int off = 16; off; off >>= 1)
        p += __shfl_down_sync(0xffffffffu, p, off);
    if (lane == 0) out[row] = p + __ldg(&bl2[0]);
}

// ---------------- launch ----------------
extern "C" void kernel_launch(void* const* d_in, const int* in_sizes, int n_in,
                              void* d_out, int out_size)
{
    const float* x    = (const float*)d_in[0];
    const int*   ei   = (const int*)  d_in[1];
    const float* W1a  = (const float*)d_in[3];
    const float* b1a  = (const float*)d_in[4];
    const float* W1b  = (const float*)d_in[5];
    const float* b1b  = (const float*)d_in[6];
    const float* W2a  = (const float*)d_in[7];
    const float* b2a  = (const float*)d_in[8];
    const float* W2b  = (const float*)d_in[9];
    const float* b2b  = (const float*)d_in[10];
    const float* Wl1  = (const float*)d_in[11];
    const float* bl1  = (const float*)d_in[12];
    const float* Wl2  = (const float*)d_in[13];
    const float* bl2  = (const float*)d_in[14];
    float* out = (float*)d_out;

    const int N = in_sizes[0] / 256;
    const int E = in_sizes[1] / 2;
    const int* src = ei;
    const int* dst = ei + E;

    __nv_bfloat16 *ah1, *al1, *ah2, *al2, *wh, *wl;
    __half* h2;
    float *x2;
    int *cnt, *cursor, *rowstart, *colsrc;
    cudaGetSymbolAddress((void**)&ah1, g_AhL1);
    cudaGetSymbolAddress((void**)&al1, g_AlL1);
    cudaGetSymbolAddress((void**)&ah2, g_AhL2);
    cudaGetSymbolAddress((void**)&al2, g_AlL2);
    cudaGetSymbolAddress((void**)&wh,  g_Wh);
    cudaGetSymbolAddress((void**)&wl,  g_Wl);
    cudaGetSymbolAddress((void**)&h2,  g_h2);
    cudaGetSymbolAddress((void**)&x2,  g_x2);
    cudaGetSymbolAddress((void**)&cnt,      g_cnt);
    cudaGetSymbolAddress((void**)&cursor,   g_cursor);
    cudaGetSymbolAddress((void**)&rowstart, g_rowstart);
    cudaGetSymbolAddress((void**)&colsrc,   g_colsrc);

    const int T = 256;
    auto blocks = [](long long work, int t) { return (int)((work + t - 1) / t); };

    // weight offsets in the packed wh/wl buffers (elements)
    const int OW1A = 0, OW1B = 16384, OW2A = 57344, OW2B = 65536;

    // ---- CSR build (shared by both layers) ----
    zero_int_kernel<<<blocks(N, T), T>>>(cnt, N);
    count_kernel<<<blocks(E, T), T>>>(dst, cnt, E);
    scan_kernel<<<1, 1024>>>(cnt, rowstart, cursor, N);
    fill_kernel<<<blocks(E, T), T>>>(src, dst, cursor, colsrc, E);

    // ---- conversions ----
    cvt_weights_kernel<<<blocks(77824 / 4, T), T>>>(
        (const float4*)W1a, 4096, (const float4*)W1b, 10240,
        (const float4*)W2a, 2048, (const float4*)W2b, 3072, wh, wl);
    cvt_plane_kernel<256, 320, 0><<<blocks((long long)N * 64, T), T>>>(
        (const float4*)x, ah1, al1, N);

    // ---- layer 1 ----
    gemm_mma<256, 64, 320, 1, 0, false><<<blocks(N, 128), 256>>>(
        ah1, al1, wh + OW1A, wl + OW1A, b1a, nullptr, h2, nullptr, nullptr, N);
    gather_mean_kernel<320, 256><<<blocks((long long)N * 32, T), T>>>(
        (const __half2*)h2, rowstart, colsrc, ah1, al1, N);
    gemm_mma<320, 128, 320, 2, 192, true><<<blocks(N, 64), 256>>>(
        ah1, al1, wh + OW1B, wl + OW1B, b1b, nullptr, nullptr, ah2, al2, N);

    // ---- layer 2 ----
    gemm_mma<128, 64, 192, 1, 0, false><<<blocks(N, 128), 256>>>(
        ah2, al2, wh + OW2A, wl + OW2A, b2a, nullptr, h2, nullptr, nullptr, N);
    gather_mean_kernel<192, 128><<<blocks((long long)N * 32, T), T>>>(
        (const __half2*)h2, rowstart, colsrc, ah2, al2, N);
    gemm_mma<192, 64, 192, 0, 0, true><<<blocks(N, 128), 256>>>(
        ah2, al2, wh + OW2B, wl + OW2B, b2b, x2, nullptr, nullptr, nullptr, N);

    // ---- head ----
    head_kernel<<<blocks((long long)N * 32, T), T>>>(x2, Wl1, bl1, Wl2, bl2, out, N);
}

// round 8
// speedup vs baseline: 2.8410x; 1.2268x over previous
#include <cuda_runtime.h>
#include <cuda_bf16.h>
#include <cuda_fp16.h>
#include <cstdint>

#define NMAX 100000
#define EMAX 3200000

// ---------------- device scratch ----------------
__device__ __nv_bfloat16 g_AGh[NMAX * 64];    // gathered means, layer-1 (bf16 hi)
__device__ __nv_bfloat16 g_AGl[NMAX * 64];    // gathered means, layer-1 (bf16 lo)
__device__ __nv_bfloat16 g_AhL2[NMAX * 192];  // layer-2 input planes
__device__ __nv_bfloat16 g_AlL2[NMAX * 192];
__device__ __nv_bfloat16 g_Wh[77824];
__device__ __nv_bfloat16 g_Wl[77824];
__device__ __half g_h2[NMAX * 64];
__device__ float  g_x2[NMAX * 64];
__device__ int    g_cnt[NMAX];
__device__ int    g_rank[EMAX];
__device__ int    g_partial[NMAX];
__device__ int    g_bsum[128];
__device__ int    g_rowstart[NMAX + 1];
__device__ int    g_colsrc[EMAX];

// ---------------- mma helpers ----------------
__device__ __forceinline__ uint32_t smem_u32(const void* p) {
    uint32_t a;
    asm("{ .reg .u64 t; cvta.to.shared.u64 t, %1; cvt.u32.u64 %0, t; }"
        : "=r"(a) : "l"(p));
    return a;
}
__device__ __forceinline__ void ldmx4(uint32_t& r0, uint32_t& r1, uint32_t& r2,
                                      uint32_t& r3, uint32_t addr) {
    asm volatile("ldmatrix.sync.aligned.m8n8.x4.shared.b16 {%0,%1,%2,%3}, [%4];"
                 : "=r"(r0), "=r"(r1), "=r"(r2), "=r"(r3) : "r"(addr));
}
__device__ __forceinline__ void ldmx4t(uint32_t& r0, uint32_t& r1, uint32_t& r2,
                                       uint32_t& r3, uint32_t addr) {
    asm volatile("ldmatrix.sync.aligned.m8n8.x4.trans.shared.b16 {%0,%1,%2,%3}, [%4];"
                 : "=r"(r0), "=r"(r1), "=r"(r2), "=r"(r3) : "r"(addr));
}
__device__ __forceinline__ void mma_bf16(float* d,
                                         uint32_t a0, uint32_t a1, uint32_t a2, uint32_t a3,
                                         uint32_t b0, uint32_t b1) {
    asm volatile("mma.sync.aligned.m16n8k16.row.col.f32.bf16.bf16.f32 "
                 "{%0,%1,%2,%3}, {%4,%5,%6,%7}, {%8,%9}, {%0,%1,%2,%3};"
                 : "+f"(d[0]), "+f"(d[1]), "+f"(d[2]), "+f"(d[3])
                 : "r"(a0), "r"(a1), "r"(a2), "r"(a3), "r"(b0), "r"(b1));
}
// split 2 floats -> packed bf16x2 hi + lo
__device__ __forceinline__ void split2(float a, float b, uint32_t& h, uint32_t& l) {
    __nv_bfloat16 ha = __float2bfloat16(a), hb = __float2bfloat16(b);
    __nv_bfloat16 la = __float2bfloat16(a - __bfloat162float(ha));
    __nv_bfloat16 lb = __float2bfloat16(b - __bfloat162float(hb));
    __nv_bfloat162 ph; ph.x = ha; ph.y = hb;
    __nv_bfloat162 pl; pl.x = la; pl.y = lb;
    h = *(uint32_t*)&ph;
    l = *(uint32_t*)&pl;
}

// ---------------- CSR build ----------------
__global__ void zero_int_kernel(int* __restrict__ p, int n) {
    int i = blockIdx.x * blockDim.x + threadIdx.x;
    if (i < n) p[i] = 0;
}
__global__ void count_rank_kernel(const int* __restrict__ dst,
                                  int* __restrict__ cnt,
                                  int* __restrict__ rank, int E) {
    int e = blockIdx.x * blockDim.x + threadIdx.x;
    if (e < E) rank[e] = atomicAdd(&cnt[dst[e]], 1);
}
__global__ void scan_blocks_kernel(const int* __restrict__ cnt,
                                   int* __restrict__ partial,
                                   int* __restrict__ bsum, int n) {
    __shared__ int ws[32];
    int tid = threadIdx.x, lane = tid & 31, wid = tid >> 5;
    int i = blockIdx.x * 1024 + tid;
    int v = (i < n) ? cnt[i] : 0;
    int x = v;
#pragma unroll
    for (int off = 1; off < 32; off <<= 1) {
        int t = __shfl_up_sync(0xffffffffu, x, off);
        if (lane >= off) x += t;
    }
    if (lane == 31) ws[wid] = x;
    __syncthreads();
    if (wid == 0) {
        int w = ws[lane];
#pragma unroll
        for (int off = 1; off < 32; off <<= 1) {
            int t = __shfl_up_sync(0xffffffffu, w, off);
            if (lane >= off) w += t;
        }
        ws[lane] = w;
    }
    __syncthreads();
    int inc = x + (wid ? ws[wid - 1] : 0);
    if (i < n) partial[i] = inc;
    if (tid == 1023) bsum[blockIdx.x] = inc;
}
__global__ void scan_sums_kernel(int* __restrict__ bsum, int nb) {
    if (threadIdx.x == 0) {
        int s = 0;
        for (int i = 0; i < nb; i++) { s += bsum[i]; bsum[i] = s; }
    }
}
__global__ void finalize_scan_kernel(const int* __restrict__ partial,
                                     const int* __restrict__ bsum,
                                     int* __restrict__ rowstart, int n) {
    int i = blockIdx.x * blockDim.x + threadIdx.x;
    if (i >= n) return;
    int b = i >> 10;
    int off = b ? bsum[b - 1] : 0;
    rowstart[i + 1] = partial[i] + off;
    if (i == 0) rowstart[0] = 0;
}
__global__ void fill2_kernel(const int* __restrict__ src, const int* __restrict__ dst,
                             const int* __restrict__ rank,
                             const int* __restrict__ rowstart,
                             int* __restrict__ colsrc, int E) {
    int e = blockIdx.x * blockDim.x + threadIdx.x;
    if (e >= E) return;
    colsrc[__ldg(&rowstart[dst[e]]) + rank[e]] = src[e];
}

// ---------------- all-weights bf16 split ----------------
__global__ void cvt_weights_kernel(const float4* __restrict__ Wa, int na4,
                                   const float4* __restrict__ Wb, int nb4,
                                   const float4* __restrict__ Wc, int nc4,
                                   const float4* __restrict__ Wd, int nd4,
                                   __nv_bfloat16* __restrict__ hi,
                                   __nv_bfloat16* __restrict__ lo) {
    int i = blockIdx.x * blockDim.x + threadIdx.x;
    int tot = na4 + nb4 + nc4 + nd4;
    if (i >= tot) return;
    float4 v;
    if (i < na4)                  v = __ldg(&Wa[i]);
    else if (i < na4 + nb4)       v = __ldg(&Wb[i - na4]);
    else if (i < na4 + nb4 + nc4) v = __ldg(&Wc[i - na4 - nb4]);
    else                          v = __ldg(&Wd[i - na4 - nb4 - nc4]);
    uint32_t h0, l0, h1, l1;
    split2(v.x, v.y, h0, l0);
    split2(v.z, v.w, h1, l1);
    size_t off = (size_t)i * 4;
    *(uint32_t*)(hi + off)     = h0;
    *(uint32_t*)(hi + off + 2) = h1;
    *(uint32_t*)(lo + off)     = l0;
    *(uint32_t*)(lo + off + 2) = l1;
}

// ---------------- CSR gather-mean: warp per node ----------------
template<int LD, int COLOFF>
__global__ void gather_mean_kernel(const __half2* __restrict__ h2,
                                   const int* __restrict__ rowstart,
                                   const int* __restrict__ colsrc,
                                   __nv_bfloat16* __restrict__ hi,
                                   __nv_bfloat16* __restrict__ lo,
                                   int n) {
    int warp = (blockIdx.x * blockDim.x + threadIdx.x) >> 5;
    int lane = threadIdx.x & 31;
    if (warp >= n) return;
    int start = __ldg(&rowstart[warp]);
    int end   = __ldg(&rowstart[warp + 1]);

    float ax0 = 0.f, ay0 = 0.f, ax1 = 0.f, ay1 = 0.f;
    float ax2 = 0.f, ay2 = 0.f, ax3 = 0.f, ay3 = 0.f;
    int i = start;
    for (; i + 4 <= end; i += 4) {
        int s0 = __ldg(&colsrc[i]);
        int s1 = __ldg(&colsrc[i + 1]);
        int s2 = __ldg(&colsrc[i + 2]);
        int s3 = __ldg(&colsrc[i + 3]);
        float2 v0 = __half22float2(__ldg(&h2[(size_t)s0 * 32 + lane]));
        float2 v1 = __half22float2(__ldg(&h2[(size_t)s1 * 32 + lane]));
        float2 v2 = __half22float2(__ldg(&h2[(size_t)s2 * 32 + lane]));
        float2 v3 = __half22float2(__ldg(&h2[(size_t)s3 * 32 + lane]));
        ax0 += v0.x; ay0 += v0.y;
        ax1 += v1.x; ay1 += v1.y;
        ax2 += v2.x; ay2 += v2.y;
        ax3 += v3.x; ay3 += v3.y;
    }
    for (; i < end; i++) {
        int s = __ldg(&colsrc[i]);
        float2 v = __half22float2(__ldg(&h2[(size_t)s * 32 + lane]));
        ax0 += v.x; ay0 += v.y;
    }
    float sx = (ax0 + ax1) + (ax2 + ax3);
    float sy = (ay0 + ay1) + (ay2 + ay3);
    float inv = 1.0f / fmaxf((float)(end - start), 1.0f);
    sx *= inv; sy *= inv;

    uint32_t h, l;
    split2(sx, sy, h, l);
    size_t off = (size_t)warp * LD + COLOFF + 2 * lane;
    *(uint32_t*)(hi + off) = h;
    *(uint32_t*)(lo + off) = l;
}

// ---------------- split-bf16 tensor-core GEMM with fused fp32-A conversion ----
// A cols [0,K1F): from fp32 Af (stride LDF), split in-kernel.
// A cols [K1F,K): from bf16 planes Ah/Al (stride LDP, col offset -K1F).
// output: 0 = fp32 Cf, 1 = fp16 Ch, 2 = bf16 hi/lo planes (Oh/Ol at LDOUT)
template<int K, int K1F, int OUT, int LDF, int LDP, int OMODE, int LDOUT, bool RELU>
__global__ __launch_bounds__(256, 2)
void gemm_mma2(const float* __restrict__ Af,
               const __nv_bfloat16* __restrict__ Ah,
               const __nv_bfloat16* __restrict__ Al,
               const __nv_bfloat16* __restrict__ Wh,
               const __nv_bfloat16* __restrict__ Wl,
               const float* __restrict__ bias,
               float* __restrict__ Cf, __half* __restrict__ Ch,
               __nv_bfloat16* __restrict__ Oh, __nv_bfloat16* __restrict__ Ol,
               int n)
{
    constexpr int BM    = (OUT == 128) ? 64 : 128;
    constexpr int BK    = 32;
    constexpr int APAD  = 40;
    constexpr int WPAD  = OUT + 8;
    constexpr int NSTG  = K / BK;
    constexpr int NWROW = BM / 16;
    constexpr int AU    = (BM * BK) / (8 * 256);
    constexpr int WU    = (BK * OUT) / (8 * 256);

    static_assert(K % BK == 0, "");
    static_assert(K1F % BK == 0, "");

    __shared__ __align__(16) __nv_bfloat16 AsH[BM * APAD];
    __shared__ __align__(16) __nv_bfloat16 AsL[BM * APAD];
    __shared__ __align__(16) __nv_bfloat16 WsH[BK * WPAD];
    __shared__ __align__(16) __nv_bfloat16 WsL[BK * WPAD];

    const int tid  = threadIdx.x;
    const int w    = tid >> 5;
    const int lane = tid & 31;
    const int wr   = w % NWROW;
    const int wc   = w / NWROW;
    const int row0 = blockIdx.x * BM;

    float d[8][4];
#pragma unroll
    for (int j = 0; j < 8; j++)
#pragma unroll
        for (int q = 0; q < 4; q++) d[j][q] = 0.f;

    uint4  paH[AU], paL[AU], pwH[WU], pwL[WU];
    float4 paf[(K1F > 0) ? 2 * AU : 1];

    auto loadA = [&](int kt) {
        if constexpr (K1F > 0) {
            if (kt < K1F) {
#pragma unroll
                for (int p = 0; p < AU; p++) {
                    int idx = tid + p * 256;
                    int r = idx >> 2, c8 = idx & 3;
                    int grow = row0 + r;
                    if (grow < n) {
                        const float4* s =
                            (const float4*)(Af + (size_t)grow * LDF + kt + c8 * 8);
                        paf[2 * p]     = s[0];
                        paf[2 * p + 1] = s[1];
                    } else {
                        paf[2 * p]     = make_float4(0.f, 0.f, 0.f, 0.f);
                        paf[2 * p + 1] = make_float4(0.f, 0.f, 0.f, 0.f);
                    }
                }
                return;
            }
        }
#pragma unroll
        for (int p = 0; p < AU; p++) {
            int idx = tid + p * 256;
            int r = idx >> 2, c8 = idx & 3;
            int grow = row0 + r;
            if (grow < n) {
                size_t off = (size_t)grow * LDP + (kt - K1F) + c8 * 8;
                paH[p] = *(const uint4*)(Ah + off);
                paL[p] = *(const uint4*)(Al + off);
            } else {
                paH[p] = make_uint4(0, 0, 0, 0);
                paL[p] = make_uint4(0, 0, 0, 0);
            }
        }
    };
    auto commitA = [&](int kt) {
        if constexpr (K1F > 0) {
            if (kt < K1F) {
#pragma unroll
                for (int p = 0; p < AU; p++) {
                    int idx = tid + p * 256;
                    int r = idx >> 2, c8 = idx & 3;
                    uint4 h4, l4;
                    float4 f0 = paf[2 * p], f1 = paf[2 * p + 1];
                    split2(f0.x, f0.y, h4.x, l4.x);
                    split2(f0.z, f0.w, h4.y, l4.y);
                    split2(f1.x, f1.y, h4.z, l4.z);
                    split2(f1.z, f1.w, h4.w, l4.w);
                    *(uint4*)(AsH + r * APAD + c8 * 8) = h4;
                    *(uint4*)(AsL + r * APAD + c8 * 8) = l4;
                }
                return;
            }
        }
#pragma unroll
        for (int p = 0; p < AU; p++) {
            int idx = tid + p * 256;
            int r = idx >> 2, c8 = idx & 3;
            *(uint4*)(AsH + r * APAD + c8 * 8) = paH[p];
            *(uint4*)(AsL + r * APAD + c8 * 8) = paL[p];
        }
    };
    auto loadW = [&](int kt) {
#pragma unroll
        for (int q = 0; q < WU; q++) {
            int idx = tid + q * 256;
            int k = idx / (OUT / 8), c8 = idx % (OUT / 8);
            size_t off = (size_t)(kt + k) * OUT + c8 * 8;
            pwH[q] = *(const uint4*)(Wh + off);
            pwL[q] = *(const uint4*)(Wl + off);
        }
    };

    loadA(0);
    loadW(0);

    const int quad = lane >> 3;
    const int l8   = lane & 7;
    const uint32_t asH = smem_u32(AsH), asL = smem_u32(AsL);
    const uint32_t wsH = smem_u32(WsH), wsL = smem_u32(WsL);
    const int aRow  = 16 * wr + (quad & 1) * 8 + l8;
    const int aColQ = (quad >> 1) * 8;
    const int bRowQ = (quad & 1) * 8 + l8;
    const int bColQ = 64 * wc + (quad >> 1) * 8;

    for (int s = 0; s < NSTG; s++) {
        commitA(s * BK);
#pragma unroll
        for (int q = 0; q < WU; q++) {
            int idx = tid + q * 256;
            int k = idx / (OUT / 8), c8 = idx % (OUT / 8);
            *(uint4*)(WsH + k * WPAD + c8 * 8) = pwH[q];
            *(uint4*)(WsL + k * WPAD + c8 * 8) = pwL[q];
        }
        __syncthreads();

        if (s + 1 < NSTG) { loadA((s + 1) * BK); loadW((s + 1) * BK); }

#pragma unroll
        for (int kk = 0; kk < BK; kk += 16) {
            uint32_t ah0, ah1, ah2, ah3, al0, al1, al2, al3;
            uint32_t aoff = (uint32_t)(aRow * APAD + kk + aColQ) * 2;
            ldmx4(ah0, ah1, ah2, ah3, asH + aoff);
            ldmx4(al0, al1, al2, al3, asL + aoff);
#pragma unroll
            for (int pr = 0; pr < 4; pr++) {
                uint32_t boff = (uint32_t)((kk + bRowQ) * WPAD + bColQ + 16 * pr) * 2;
                uint32_t bh0, bh1, bh2, bh3, bl0, bl1, bl2, bl3;
                ldmx4t(bh0, bh1, bh2, bh3, wsH + boff);
                ldmx4t(bl0, bl1, bl2, bl3, wsL + boff);
                mma_bf16(d[2 * pr],     ah0, ah1, ah2, ah3, bh0, bh1);
                mma_bf16(d[2 * pr],     ah0, ah1, ah2, ah3, bl0, bl1);
                mma_bf16(d[2 * pr],     al0, al1, al2, al3, bh0, bh1);
                mma_bf16(d[2 * pr + 1], ah0, ah1, ah2, ah3, bh2, bh3);
                mma_bf16(d[2 * pr + 1], ah0, ah1, ah2, ah3, bl2, bl3);
                mma_bf16(d[2 * pr + 1], al0, al1, al2, al3, bh2, bh3);
            }
        }
        __syncthreads();
    }

    const int tr = lane >> 2;
    const int tc = (lane & 3) * 2;
#pragma unroll
    for (int j = 0; j < 8; j++) {
        int c = 64 * wc + 8 * j + tc;
        float b0 = __ldg(&bias[c]);
        float b1 = __ldg(&bias[c + 1]);
#pragma unroll
        for (int half = 0; half < 2; half++) {
            int r = row0 + 16 * wr + tr + 8 * half;
            if (r >= n) continue;
            float v0 = d[j][2 * half]     + b0;
            float v1 = d[j][2 * half + 1] + b1;
            if (RELU) { v0 = fmaxf(v0, 0.f); v1 = fmaxf(v1, 0.f); }
            if constexpr (OMODE == 0) {
                *(float2*)&Cf[(size_t)r * OUT + c] = make_float2(v0, v1);
            } else if constexpr (OMODE == 1) {
                *(__half2*)&Ch[(size_t)r * OUT + c] = __floats2half2_rn(v0, v1);
            } else {
                uint32_t h, l;
                split2(v0, v1, h, l);
                *(uint32_t*)(Oh + (size_t)r * LDOUT + c) = h;
                *(uint32_t*)(Ol + (size_t)r * LDOUT + c) = l;
            }
        }
    }
}

// ---------------- head ----------------
__global__ void head_kernel(const float* __restrict__ x2,
                            const float* __restrict__ Wl1,
                            const float* __restrict__ bl1,
                            const float* __restrict__ Wl2,
                            const float* __restrict__ bl2,
                            float* __restrict__ out, int n)
{
    int gtid = blockIdx.x * blockDim.x + threadIdx.x;
    int row  = gtid >> 5;
    int lane = gtid & 31;
    if (row >= n) return;
    const float* xr = x2 + (size_t)row * 64;
    float acc = 0.f;
#pragma unroll
    for (int k = 0; k < 64; k++)
        acc = fmaf(__ldg(&xr[k]), __ldg(&Wl1[k * 32 + lane]), acc);
    float h = fmaxf(acc + __ldg(&bl1[lane]), 0.f);
    float p = h * __ldg(&Wl2[lane]);
#pragma unroll
    for (int off = 16; off; off >>= 1)
        p += __shfl_down_sync(0xffffffffu, p, off);
    if (lane == 0) out[row] = p + __ldg(&bl2[0]);
}

// ---------------- launch ----------------
extern "C" void kernel_launch(void* const* d_in, const int* in_sizes, int n_in,
                              void* d_out, int out_size)
{
    const float* x    = (const float*)d_in[0];
    const int*   ei   = (const int*)  d_in[1];
    const float* W1a  = (const float*)d_in[3];
    const float* b1a  = (const float*)d_in[4];
    const float* W1b  = (const float*)d_in[5];
    const float* b1b  = (const float*)d_in[6];
    const float* W2a  = (const float*)d_in[7];
    const float* b2a  = (const float*)d_in[8];
    const float* W2b  = (const float*)d_in[9];
    const float* b2b  = (const float*)d_in[10];
    const float* Wl1  = (const float*)d_in[11];
    const float* bl1  = (const float*)d_in[12];
    const float* Wl2  = (const float*)d_in[13];
    const float* bl2  = (const float*)d_in[14];
    float* out = (float*)d_out;

    const int N = in_sizes[0] / 256;
    const int E = in_sizes[1] / 2;
    const int* src = ei;
    const int* dst = ei + E;

    __nv_bfloat16 *agh, *agl, *ah2, *al2, *wh, *wl;
    __half* h2;
    float *x2;
    int *cnt, *rank, *partial, *bsum, *rowstart, *colsrc;
    cudaGetSymbolAddress((void**)&agh, g_AGh);
    cudaGetSymbolAddress((void**)&agl, g_AGl);
    cudaGetSymbolAddress((void**)&ah2, g_AhL2);
    cudaGetSymbolAddress((void**)&al2, g_AlL2);
    cudaGetSymbolAddress((void**)&wh,  g_Wh);
    cudaGetSymbolAddress((void**)&wl,  g_Wl);
    cudaGetSymbolAddress((void**)&h2,  g_h2);
    cudaGetSymbolAddress((void**)&x2,  g_x2);
    cudaGetSymbolAddress((void**)&cnt,      g_cnt);
    cudaGetSymbolAddress((void**)&rank,     g_rank);
    cudaGetSymbolAddress((void**)&partial,  g_partial);
    cudaGetSymbolAddress((void**)&bsum,     g_bsum);
    cudaGetSymbolAddress((void**)&rowstart, g_rowstart);
    cudaGetSymbolAddress((void**)&colsrc,   g_colsrc);

    const int T = 256;
    auto blocks = [](long long work, int t) { return (int)((work + t - 1) / t); };
    const int NB = blocks(N, 1024);

    // weight offsets in packed wh/wl (elements)
    const int OW1A = 0, OW1B = 16384, OW2A = 57344, OW2B = 65536;

    // ---- CSR build (rank-based, atomic-free fill) ----
    zero_int_kernel<<<blocks(N, T), T>>>(cnt, N);
    count_rank_kernel<<<blocks(E, T), T>>>(dst, cnt, rank, E);
    scan_blocks_kernel<<<NB, 1024>>>(cnt, partial, bsum, N);
    scan_sums_kernel<<<1, 32>>>(bsum, NB);
    finalize_scan_kernel<<<blocks(N, T), T>>>(partial, bsum, rowstart, N);
    fill2_kernel<<<blocks(E, T), T>>>(src, dst, rank, rowstart, colsrc, E);

    // ---- weights ----
    cvt_weights_kernel<<<blocks(77824 / 4, T), T>>>(
        (const float4*)W1a, 4096, (const float4*)W1b, 10240,
        (const float4*)W2a, 2048, (const float4*)W2b, 3072, wh, wl);

    // ---- layer 1 (x read as fp32, converted in-GEMM) ----
    gemm_mma2<256, 256, 64, 256, 64, 1, 0, false><<<blocks(N, 128), 256>>>(
        x, agh, agl, wh + OW1A, wl + OW1A, b1a, nullptr, h2, nullptr, nullptr, N);
    gather_mean_kernel<64, 0><<<blocks((long long)N * 32, T), T>>>(
        (const __half2*)h2, rowstart, colsrc, agh, agl, N);
    gemm_mma2<320, 256, 128, 256, 64, 2, 192, true><<<blocks(N, 64), 256>>>(
        x, agh, agl, wh + OW1B, wl + OW1B, b1b, nullptr, nullptr, ah2, al2, N);

    // ---- layer 2 (bf16 planes throughout) ----
    gemm_mma2<128, 0, 64, 0, 192, 1, 0, false><<<blocks(N, 128), 256>>>(
        nullptr, ah2, al2, wh + OW2A, wl + OW2A, b2a, nullptr, h2, nullptr, nullptr, N);
    gather_mean_kernel<192, 128><<<blocks((long long)N * 32, T), T>>>(
        (const __half2*)h2, rowstart, colsrc, ah2, al2, N);
    gemm_mma2<192, 0, 64, 0, 192, 0, 0, true><<<blocks(N, 128), 256>>>(
        nullptr, ah2, al2, wh + OW2B, wl + OW2B, b2b, x2, nullptr, nullptr, nullptr, N);

    // ---- head ----
    head_kernel<<<blocks((long long)N * 32, T), T>>>(x2, Wl1, bl1, Wl2, bl2, out, N);
}